// round 5
// baseline (speedup 1.0000x reference)
#include <cuda_runtime.h>
#include <cuda_bf16.h>
#include <float.h>
#include <math.h>

#define NN     50000
#define EEDGE  800000
#define ETOT   (EEDGE + NN)

// ---------------- device scratch ----------------
__device__ float g_bufA[(size_t)NN * 256];
__device__ float g_bufB[(size_t)NN * 256];
__device__ float g_es[(size_t)NN * 4];
__device__ float g_ed[(size_t)NN * 4];
__device__ int   g_cnt[NN];
__device__ int   g_cursor[NN];
__device__ int   g_row_ptr[NN + 1];
__device__ int   g_col_src[ETOT];
__device__ int   g_part[64];

// ---------------- tf32 helpers ----------------
__device__ __forceinline__ unsigned tf32h(float x) {
    unsigned u;
    asm("cvt.rna.tf32.f32 %0, %1;" : "=r"(u) : "f"(x));
    return u;
}
__device__ __forceinline__ void mma_tf32(float* c, const unsigned* a, const unsigned* b) {
    asm volatile("mma.sync.aligned.m16n8k8.row.col.f32.tf32.tf32.f32 "
        "{%0,%1,%2,%3}, {%4,%5,%6,%7}, {%8,%9}, {%0,%1,%2,%3};"
        : "+f"(c[0]), "+f"(c[1]), "+f"(c[2]), "+f"(c[3])
        : "r"(a[0]), "r"(a[1]), "r"(a[2]), "r"(a[3]), "r"(b[0]), "r"(b[1]));
}

// ---------------- CSR construction ----------------
__global__ void k_zero_int(int* __restrict__ p, int n) {
    int i = blockIdx.x * blockDim.x + threadIdx.x;
    if (i < n) p[i] = 0;
}

__global__ void k_hist(const int* __restrict__ ei, int E, int n, int* __restrict__ cnt) {
    int i = blockIdx.x * blockDim.x + threadIdx.x;
    int tot = E + n;
    if (i < tot) {
        int d = (i < E) ? ei[E + i] : (i - E);
        atomicAdd(&cnt[d], 1);
    }
}

// stage 1: per-block inclusive scan -> row_ptr (temp), block totals -> part
__global__ void k_scan1(const int* __restrict__ cnt, int n,
                        int* __restrict__ incl, int* __restrict__ part) {
    __shared__ int sh[1024];
    const int t = threadIdx.x;
    const int i = blockIdx.x * 1024 + t;
    int v = (i < n) ? cnt[i] : 0;
    sh[t] = v;
    __syncthreads();
    #pragma unroll
    for (int o = 1; o < 1024; o <<= 1) {
        int add = (t >= o) ? sh[t - o] : 0;
        __syncthreads();
        sh[t] += add;
        __syncthreads();
    }
    if (i < n) incl[i] = sh[t];
    if (t == 1023) part[blockIdx.x] = sh[1023];
}

// stage 2+3 fused: each block computes its own offset from block totals
__global__ void k_scan23(const int* __restrict__ cnt, int n,
                         int* __restrict__ row_ptr, int* __restrict__ cursor,
                         const int* __restrict__ part) {
    __shared__ int soff;
    const int t = threadIdx.x;
    if (t < 32) {
        int s = 0;
        for (int i = t; i < (int)blockIdx.x; i += 32) s += part[i];
        #pragma unroll
        for (int o = 16; o; o >>= 1) s += __shfl_xor_sync(0xffffffffu, s, o);
        if (t == 0) soff = s;
    }
    __syncthreads();
    const int i = blockIdx.x * 1024 + t;
    if (i < n) {
        int incl = row_ptr[i];
        int c = cnt[i];
        int exc = incl - c + soff;
        row_ptr[i] = exc;
        cursor[i] = exc;
        if (i == n - 1) row_ptr[n] = exc + c;
    }
}

__global__ void k_scatter(const int* __restrict__ ei, int E, int n,
                          int* __restrict__ cursor, int* __restrict__ col_src) {
    int i = blockIdx.x * blockDim.x + threadIdx.x;
    int tot = E + n;
    if (i < tot) {
        int s = (i < E) ? ei[i]     : (i - E);
        int d = (i < E) ? ei[E + i] : (i - E);
        int pos = atomicAdd(&cursor[d], 1);
        col_src[pos] = s;
    }
}

// ---------------- GEMM, K=16 (layer 1) ----------------
__global__ void k_gemm16(const float* __restrict__ X, const float* __restrict__ W,
                         float* __restrict__ O, int nrows) {
    __shared__ float Wsh[16 * 256];
    __shared__ float Xsh[16 * 16];
    const int t = threadIdx.x;
    for (int i = t; i < 16 * 256; i += 256) Wsh[i] = W[i];
    const int r0 = blockIdx.x * 16;
    {
        int r = t >> 4, c = t & 15;
        int rr = r0 + r; if (rr >= nrows) rr = nrows - 1;
        Xsh[t] = X[(size_t)rr * 16 + c];
    }
    __syncthreads();
    float acc[16];
    #pragma unroll
    for (int r = 0; r < 16; r++) acc[r] = 0.f;
    #pragma unroll
    for (int k = 0; k < 16; k++) {
        float w = Wsh[k * 256 + t];
        #pragma unroll
        for (int r = 0; r < 16; r++) acc[r] = fmaf(Xsh[r * 16 + k], w, acc[r]);
    }
    #pragma unroll
    for (int r = 0; r < 16; r++) {
        int rr = r0 + r;
        if (rr < nrows) O[(size_t)rr * 256 + t] = acc[r];
    }
}

// ---------------- tf32x3 tensor GEMM + fused attention dots epilogue ----------------
// block: 256 thr (8 warps 4x2), tile 128 rows x 64 cols; each block's 64-col slice
// is exactly one head -> compute es/ed for its rows locally.
template <int NT, int H>
__global__ void __launch_bounds__(256)
k_gemm_tf32(const float* __restrict__ X, const float* __restrict__ W,
            float* __restrict__ O, int nrows,
            const float* __restrict__ As, const float* __restrict__ Ad,
            float* __restrict__ esv, float* __restrict__ edv) {
    __shared__ __align__(16) float Xs[128][36];
    __shared__ __align__(16) float Ws[32][72];
    __shared__ float esr[128], edr[128];

    const int t = threadIdx.x;
    const int lane = t & 31;
    const int w = t >> 5;
    const int warp_m = w >> 1;
    const int warp_n = w & 1;
    const int lr = lane >> 2;
    const int lc = lane & 3;
    const int r0 = blockIdx.x * 128;
    const int n0 = blockIdx.y * 64;
    const int head = blockIdx.y;

    float acc[2][4][4];
    #pragma unroll
    for (int mt = 0; mt < 2; mt++)
        #pragma unroll
        for (int nt = 0; nt < 4; nt++)
            #pragma unroll
            for (int i = 0; i < 4; i++) acc[mt][nt][i] = 0.f;

    for (int k0 = 0; k0 < 256; k0 += 32) {
        __syncthreads();
        #pragma unroll
        for (int j = 0; j < 4; j++) {
            int idx = t + j * 256;
            int row = idx >> 3, c4 = idx & 7;
            int rr = r0 + row; if (rr >= nrows) rr = nrows - 1;
            *reinterpret_cast<float4*>(&Xs[row][c4 * 4]) =
                *reinterpret_cast<const float4*>(X + (size_t)rr * 256 + k0 + c4 * 4);
        }
        #pragma unroll
        for (int j = 0; j < 2; j++) {
            int idx = t + j * 256;
            int row = idx >> 4, c4 = idx & 15;
            *reinterpret_cast<float4*>(&Ws[row][c4 * 4]) =
                *reinterpret_cast<const float4*>(W + (size_t)(k0 + row) * NT + n0 + c4 * 4);
        }
        __syncthreads();

        #pragma unroll
        for (int ks = 0; ks < 4; ks++) {
            const int kk = ks * 8;
            unsigned bhi[4][2], blo[4][2];
            #pragma unroll
            for (int nt = 0; nt < 4; nt++) {
                int cb = warp_n * 32 + nt * 8 + lr;
                float b0 = Ws[kk + lc][cb];
                float b1 = Ws[kk + lc + 4][cb];
                bhi[nt][0] = tf32h(b0);
                bhi[nt][1] = tf32h(b1);
                blo[nt][0] = tf32h(b0 - __uint_as_float(bhi[nt][0]));
                blo[nt][1] = tf32h(b1 - __uint_as_float(bhi[nt][1]));
            }
            #pragma unroll
            for (int mt = 0; mt < 2; mt++) {
                int ar = warp_m * 32 + mt * 16 + lr;
                float a0 = Xs[ar][kk + lc];
                float a1 = Xs[ar + 8][kk + lc];
                float a2 = Xs[ar][kk + lc + 4];
                float a3 = Xs[ar + 8][kk + lc + 4];
                unsigned ah[4] = {tf32h(a0), tf32h(a1), tf32h(a2), tf32h(a3)};
                unsigned al[4] = {tf32h(a0 - __uint_as_float(ah[0])),
                                  tf32h(a1 - __uint_as_float(ah[1])),
                                  tf32h(a2 - __uint_as_float(ah[2])),
                                  tf32h(a3 - __uint_as_float(ah[3]))};
                #pragma unroll
                for (int nt = 0; nt < 4; nt++) {
                    mma_tf32(acc[mt][nt], al, bhi[nt]);
                    mma_tf32(acc[mt][nt], ah, blo[nt]);
                    mma_tf32(acc[mt][nt], ah, bhi[nt]);
                }
            }
        }
    }

    #pragma unroll
    for (int mt = 0; mt < 2; mt++) {
        #pragma unroll
        for (int nt = 0; nt < 4; nt++) {
            int row = r0 + warp_m * 32 + mt * 16 + lr;
            int colg = n0 + warp_n * 32 + nt * 8 + lc * 2;
            if (row < nrows) {
                float2 v0 = make_float2(acc[mt][nt][0], acc[mt][nt][1]);
                *reinterpret_cast<float2*>(O + (size_t)row * NT + colg) = v0;
            }
            if (row + 8 < nrows) {
                float2 v1 = make_float2(acc[mt][nt][2], acc[mt][nt][3]);
                *reinterpret_cast<float2*>(O + (size_t)(row + 8) * NT + colg) = v1;
            }
        }
    }

    // ---- fused dots epilogue ----
    for (int i = t; i < 128; i += 256) { esr[i] = 0.f; edr[i] = 0.f; }
    __syncthreads();
    float pes[4] = {0, 0, 0, 0}, ped[4] = {0, 0, 0, 0};
    #pragma unroll
    for (int nt = 0; nt < 4; nt++) {
        int cb = warp_n * 32 + nt * 8 + lc * 2;
        float as0 = As[head * 64 + cb], as1 = As[head * 64 + cb + 1];
        float ad0 = Ad[head * 64 + cb], ad1 = Ad[head * 64 + cb + 1];
        #pragma unroll
        for (int mt = 0; mt < 2; mt++) {
            pes[mt * 2 + 0] += acc[mt][nt][0] * as0 + acc[mt][nt][1] * as1;
            pes[mt * 2 + 1] += acc[mt][nt][2] * as0 + acc[mt][nt][3] * as1;
            ped[mt * 2 + 0] += acc[mt][nt][0] * ad0 + acc[mt][nt][1] * ad1;
            ped[mt * 2 + 1] += acc[mt][nt][2] * ad0 + acc[mt][nt][3] * ad1;
        }
    }
    #pragma unroll
    for (int j = 0; j < 4; j++) {
        #pragma unroll
        for (int o = 1; o <= 2; o <<= 1) {
            pes[j] += __shfl_xor_sync(0xffffffffu, pes[j], o);
            ped[j] += __shfl_xor_sync(0xffffffffu, ped[j], o);
        }
    }
    if (lc == 0) {
        #pragma unroll
        for (int j = 0; j < 4; j++) {
            int rl = warp_m * 32 + (j >> 1) * 16 + lr + (j & 1) * 8;
            atomicAdd(&esr[rl], pes[j]);
            atomicAdd(&edr[rl], ped[j]);
        }
    }
    __syncthreads();
    if (t < 128) {
        int row = r0 + t;
        if (row < nrows) {
            esv[(size_t)row * H + head] = esr[t];
            edv[(size_t)row * H + head] = edr[t];
        }
    }
}

// ---------------- attention dot products (layer 1 only) ----------------
template <int H>
__global__ void k_dots(const float* __restrict__ Hm, const float* __restrict__ As,
                       const float* __restrict__ Ad, float* __restrict__ es,
                       float* __restrict__ ed) {
    const int node = blockIdx.x;
    const int w = threadIdx.x >> 5;
    const int l = threadIdx.x & 31;
    const float* hp = Hm + (size_t)node * (H * 64) + w * 64;
    float s1 = fmaf(hp[l], As[w * 64 + l], hp[l + 32] * As[w * 64 + l + 32]);
    float s2 = fmaf(hp[l], Ad[w * 64 + l], hp[l + 32] * Ad[w * 64 + l + 32]);
    #pragma unroll
    for (int o = 16; o; o >>= 1) {
        s1 += __shfl_xor_sync(0xffffffffu, s1, o);
        s2 += __shfl_xor_sync(0xffffffffu, s2, o);
    }
    if (l == 0) { es[node * H + w] = s1; ed[node * H + w] = s2; }
}

// ---------------- fused softmax + aggregation (persistent) ----------------
template <int H, bool ELU>
__global__ void __launch_bounds__(H * 64)
k_fused(const float* __restrict__ Hm, const float* __restrict__ es,
        const float* __restrict__ ed, const int* __restrict__ row_ptr,
        const int* __restrict__ col, const float* __restrict__ bias,
        float* __restrict__ out, int n) {
    constexpr int F = H * 64;
    constexpr int CAP = 512;
    const int t = threadIdx.x;
    const int head = t >> 6;
    const int w = t >> 5;
    const int l = t & 31;

    __shared__ int   scol[CAP];
    __shared__ float se[H][CAP];
    __shared__ float sinv[H];
    __shared__ float m_sh[H], den_sh[H], scale_sh[H], cmax[H], csum[H];

    const float bi = bias[t];

    for (int node = blockIdx.x; node < n; node += gridDim.x) {
        const int beg = row_ptr[node];
        const int end = row_ptr[node + 1];
        const int deg = end - beg;

        if (deg == 0) {
            float r = bi;
            if (ELU) r = (r > 0.f) ? r : expm1f(r);
            out[(size_t)node * F + t] = r;
            continue;
        }

        if (deg <= CAP) {
            for (int i = t; i < deg; i += F) scol[i] = col[beg + i];
            __syncthreads();

            if (w < H) {
                const float edl = ed[node * H + w];
                float mm = -FLT_MAX;
                for (int c = l; c < deg; c += 32) {
                    float e = es[scol[c] * H + w] + edl;
                    e = (e > 0.f) ? e : 0.2f * e;
                    se[w][c] = e;
                    mm = fmaxf(mm, e);
                }
                #pragma unroll
                for (int o = 16; o; o >>= 1) mm = fmaxf(mm, __shfl_xor_sync(0xffffffffu, mm, o));
                float ss = 0.f;
                for (int c = l; c < deg; c += 32) {
                    float ex = __expf(se[w][c] - mm);
                    se[w][c] = ex;
                    ss += ex;
                }
                #pragma unroll
                for (int o = 16; o; o >>= 1) ss += __shfl_xor_sync(0xffffffffu, ss, o);
                if (l == 0) sinv[w] = 1.0f / ss;
            }
            __syncthreads();

            float a0 = 0.f, a1 = 0.f, a2 = 0.f, a3 = 0.f;
            float a4 = 0.f, a5 = 0.f, a6 = 0.f, a7 = 0.f;
            int c = 0;
            for (; c + 8 <= deg; c += 8) {
                int s0 = scol[c],     s1 = scol[c + 1], s2 = scol[c + 2], s3 = scol[c + 3];
                int s4 = scol[c + 4], s5 = scol[c + 5], s6 = scol[c + 6], s7 = scol[c + 7];
                float w0 = se[head][c],     w1 = se[head][c + 1];
                float w2 = se[head][c + 2], w3 = se[head][c + 3];
                float w4 = se[head][c + 4], w5 = se[head][c + 5];
                float w6 = se[head][c + 6], w7 = se[head][c + 7];
                a0 = fmaf(Hm[(size_t)s0 * F + t], w0, a0);
                a1 = fmaf(Hm[(size_t)s1 * F + t], w1, a1);
                a2 = fmaf(Hm[(size_t)s2 * F + t], w2, a2);
                a3 = fmaf(Hm[(size_t)s3 * F + t], w3, a3);
                a4 = fmaf(Hm[(size_t)s4 * F + t], w4, a4);
                a5 = fmaf(Hm[(size_t)s5 * F + t], w5, a5);
                a6 = fmaf(Hm[(size_t)s6 * F + t], w6, a6);
                a7 = fmaf(Hm[(size_t)s7 * F + t], w7, a7);
            }
            for (; c < deg; c++)
                a0 = fmaf(Hm[(size_t)scol[c] * F + t], se[head][c], a0);

            float res = ((a0 + a1) + (a2 + a3)) + ((a4 + a5) + (a6 + a7));
            res = res * sinv[head] + bi;
            if (ELU) res = (res > 0.f) ? res : expm1f(res);
            out[(size_t)node * F + t] = res;
            __syncthreads();
        } else {
            // chunked online-softmax fallback (deg > CAP; essentially never)
            if (t < H) { m_sh[t] = -FLT_MAX; den_sh[t] = 0.f; }
            float acc = 0.f;
            const float edl = (w < H) ? ed[node * H + w] : 0.f;
            __syncthreads();
            for (int ch = beg; ch < end; ch += CAP) {
                const int len = min(CAP, end - ch);
                for (int i = t; i < len; i += F) scol[i] = col[ch + i];
                __syncthreads();
                if (w < H) {
                    float mm = -FLT_MAX;
                    for (int c = l; c < len; c += 32) {
                        float e = es[scol[c] * H + w] + edl;
                        e = (e > 0.f) ? e : 0.2f * e;
                        se[w][c] = e;
                        mm = fmaxf(mm, e);
                    }
                    #pragma unroll
                    for (int o = 16; o; o >>= 1) mm = fmaxf(mm, __shfl_xor_sync(0xffffffffu, mm, o));
                    if (l == 0) cmax[w] = mm;
                }
                __syncthreads();
                if (t < H) {
                    float nm = fmaxf(m_sh[t], cmax[t]);
                    float sc = __expf(m_sh[t] - nm);
                    scale_sh[t] = sc;
                    m_sh[t] = nm;
                    den_sh[t] *= sc;
                }
                __syncthreads();
                if (w < H) {
                    float ss = 0.f;
                    const float nm = m_sh[w];
                    for (int c = l; c < len; c += 32) {
                        float ex = __expf(se[w][c] - nm);
                        se[w][c] = ex;
                        ss += ex;
                    }
                    #pragma unroll
                    for (int o = 16; o; o >>= 1) ss += __shfl_xor_sync(0xffffffffu, ss, o);
                    if (l == 0) csum[w] = ss;
                }
                acc *= scale_sh[head];
                __syncthreads();
                if (t < H) den_sh[t] += csum[t];
                for (int c = 0; c < len; c++)
                    acc = fmaf(Hm[(size_t)scol[c] * F + t], se[head][c], acc);
                __syncthreads();
            }
            float res = acc / den_sh[head] + bi;
            if (ELU) res = (res > 0.f) ? res : expm1f(res);
            out[(size_t)node * F + t] = res;
            __syncthreads();
        }
    }
}

// ---------------- graph embedding mean ----------------
__global__ void k_zero_f(float* __restrict__ p, int n) {
    int i = blockIdx.x * blockDim.x + threadIdx.x;
    if (i < n) p[i] = 0.f;
}

__global__ void k_mean(const float* __restrict__ node_emb, float* __restrict__ out, int n) {
    const int t = threadIdx.x;  // 64
    float a = 0.f;
    for (int r = blockIdx.x; r < n; r += gridDim.x)
        a += node_emb[(size_t)r * 64 + t];
    atomicAdd(&out[t], a * (1.0f / (float)n));
}

// ---------------- launch ----------------
extern "C" void kernel_launch(void* const* d_in, const int* in_sizes, int n_in,
                              void* d_out, int out_size) {
    const float* x   = (const float*)d_in[0];
    const int*   ei  = (const int*)d_in[1];
    const float* W1  = (const float*)d_in[2];
    const float* a1s = (const float*)d_in[3];
    const float* a1d = (const float*)d_in[4];
    const float* b1  = (const float*)d_in[5];
    const float* W2  = (const float*)d_in[6];
    const float* a2s = (const float*)d_in[7];
    const float* a2d = (const float*)d_in[8];
    const float* b2  = (const float*)d_in[9];
    const float* W3  = (const float*)d_in[10];
    const float* a3s = (const float*)d_in[11];
    const float* a3d = (const float*)d_in[12];
    const float* b3  = (const float*)d_in[13];
    float* out = (float*)d_out;

    const int n = in_sizes[0] / 16;   // 50000
    const int E = in_sizes[1] / 2;    // 800000
    const int tot = E + n;
    const int B = (n + 1023) / 1024;

    float *bufA, *bufB, *es, *ed;
    int *cnt, *cursor, *row_ptr, *col, *part;
    cudaGetSymbolAddress((void**)&bufA, g_bufA);
    cudaGetSymbolAddress((void**)&bufB, g_bufB);
    cudaGetSymbolAddress((void**)&es, g_es);
    cudaGetSymbolAddress((void**)&ed, g_ed);
    cudaGetSymbolAddress((void**)&cnt, g_cnt);
    cudaGetSymbolAddress((void**)&cursor, g_cursor);
    cudaGetSymbolAddress((void**)&row_ptr, g_row_ptr);
    cudaGetSymbolAddress((void**)&col, g_col_src);
    cudaGetSymbolAddress((void**)&part, g_part);

    // CSR by dst (5 launches)
    k_zero_int<<<(n + 255) / 256, 256>>>(cnt, n);
    k_hist<<<(tot + 255) / 256, 256>>>(ei, E, n, cnt);
    k_scan1<<<B, 1024>>>(cnt, n, row_ptr, part);
    k_scan23<<<B, 1024>>>(cnt, n, row_ptr, cursor, part);
    k_scatter<<<(tot + 255) / 256, 256>>>(ei, E, n, cursor, col);

    // layer 1
    k_gemm16<<<(n + 15) / 16, 256>>>(x, W1, bufA, n);
    k_dots<4><<<n, 128>>>(bufA, a1s, a1d, es, ed);
    k_fused<4, true><<<1184, 256>>>(bufA, es, ed, row_ptr, col, b1, bufB, n);

    // layer 2 (tf32x3 GEMM + fused dots)
    {
        dim3 g((n + 127) / 128, 4);
        k_gemm_tf32<256, 4><<<g, 256>>>(bufB, W2, bufA, n, a2s, a2d, es, ed);
    }
    k_fused<4, true><<<1184, 256>>>(bufA, es, ed, row_ptr, col, b2, bufB, n);

    // layer 3 (tf32x3 GEMM + fused dots, N=64)
    {
        dim3 g((n + 127) / 128, 1);
        k_gemm_tf32<64, 1><<<g, 256>>>(bufB, W3, bufA, n, a3s, a3d, es, ed);
    }
    k_fused<1, false><<<2368, 64>>>(bufA, es, ed, row_ptr, col, b3, out, n);

    // graph embedding
    k_zero_f<<<1, 64>>>(out + (size_t)n * 64, 64);
    k_mean<<<256, 64>>>(out, out + (size_t)n * 64, n);
}